// round 3
// baseline (speedup 1.0000x reference)
#include <cuda_runtime.h>
#include <cuda_bf16.h>

#define H     128
#define BATCH 8
#define TQ    512
#define TK    512

// Device scratch (allocation-free rule: __device__ globals)
__device__ __align__(16) float g_qp[BATCH * TQ * H];
__device__ __align__(16) float g_kp[BATCH * TK * H];

__device__ __forceinline__ float tanha(float x) {
    float y;
    asm("tanh.approx.f32 %0, %1;" : "=f"(y) : "f"(x));
    return y;
}

// ---------------------------------------------------------------------------
// Kernel 1: projections  qp = queries @ Wa_w^T + Wa_b ; kp = keys @ Ua_w^T + Ua_b
// grid = (T/16, B, 2), block = 128 (one thread per output column h)
// ---------------------------------------------------------------------------
__global__ void __launch_bounds__(128) proj_kernel(
    const float* __restrict__ queries, const float* __restrict__ keys,
    const float* __restrict__ Wa_w, const float* __restrict__ Wa_b,
    const float* __restrict__ Ua_w, const float* __restrict__ Ua_b)
{
    const int tile = blockIdx.x;   // 32 tiles of 16 rows
    const int b    = blockIdx.y;
    const int proj = blockIdx.z;

    const float* x    = proj == 0 ? queries : keys;
    const float* W    = proj == 0 ? Wa_w    : Ua_w;
    const float* bias = proj == 0 ? Wa_b    : Ua_b;
    float*       out  = proj == 0 ? g_qp    : g_kp;

    const int t0 = tile * 16;
    __shared__ __align__(16) float xs[16][H];

    const float4* xsrc = (const float4*)(x + (size_t)(b * 512 + t0) * H);
    #pragma unroll
    for (int i = threadIdx.x; i < 16 * H / 4; i += 128)
        ((float4*)xs)[i] = xsrc[i];
    __syncthreads();

    const int h = threadIdx.x;
    float acc[16];
    const float bv = bias[h];
    #pragma unroll
    for (int t = 0; t < 16; t++) acc[t] = bv;

    const float4* Wrow = (const float4*)(W + h * H);
    #pragma unroll 4
    for (int i = 0; i < H / 4; i++) {
        float4 w4 = Wrow[i];
        #pragma unroll
        for (int t = 0; t < 16; t++) {
            float4 xv = ((const float4*)xs[t])[i];
            acc[t] = fmaf(xv.x, w4.x, fmaf(xv.y, w4.y, fmaf(xv.z, w4.z, fmaf(xv.w, w4.w, acc[t]))));
        }
    }

    #pragma unroll
    for (int t = 0; t < 16; t++)
        out[(size_t)(b * 512 + t0 + t) * H + h] = acc[t];
}

// ---------------------------------------------------------------------------
// Kernel 2: scores (tanh additive attention) + softmax + context
// grid = (TQ/8, B), block = 256 (8 warps, one query per warp)
// Lane <-> key mapping: each lane owns 1 key of a 32-key tile, serial over h.
// smem (40960 B < 48KB default cap):
//   tile[128][32] transposed kp (16KB, reused as keys[32][128] in phase C)
//   sc[8][512] scores (16KB)
//   qva[8][128] float2 {q[h], Va[h]} (8KB)
// ---------------------------------------------------------------------------
__global__ void __launch_bounds__(256) attn_kernel(
    const float* __restrict__ keys,
    const float* __restrict__ Va_w,
    float* __restrict__ ctx_out,   // (B, TQ, H)
    float* __restrict__ w_out)     // (B, TQ, TK)
{
    extern __shared__ __align__(16) float smem[];
    float*  tile = smem;                       // 32*128 floats (16 KB)
    float*  sc   = smem + 32 * H;              // 8*512 floats  (16 KB)
    float2* qva  = (float2*)(sc + 8 * TK);     // 8*128 float2  (8 KB)

    const int b    = blockIdx.y;
    const int wid  = threadIdx.x >> 5;
    const int lane = threadIdx.x & 31;
    const int q    = blockIdx.x * 8 + wid;

    // Stage interleaved {q[h], Va[h]} pairs: 1024 entries, 4 per thread
    {
        const float* qbase = g_qp + (size_t)(b * TQ + blockIdx.x * 8) * H;
        #pragma unroll
        for (int r = 0; r < 4; r++) {
            int i  = threadIdx.x + 256 * r;    // 0..1023
            int qq = i >> 7;                   // query row 0..7
            int hh = i & 127;                  // h index
            qva[i] = make_float2(qbase[qq * H + hh], Va_w[hh]);
        }
    }

    const float2* myqva = qva + wid * H;

    // ---- Phase A: scores[q][k] = sum_h Va[h] * tanh(qp[h] + kp_t[h][k]) ----
    for (int kt = 0; kt < TK; kt += 32) {
        __syncthreads();  // protects prior tile reads + (first iter) qva stores
        // Cooperative transposed load: g_kp[kt+k][h] -> tile[h][k]
        const float4* src4 = (const float4*)(g_kp + (size_t)(b * TK + kt) * H);
        #pragma unroll
        for (int r = 0; r < 4; r++) {
            int idx = threadIdx.x + 256 * r;   // 0..1023
            int k   = idx & 31;
            int h4  = idx >> 5;                // 0..31
            float4 v = src4[k * (H / 4) + h4];
            tile[(4 * h4 + 0) * 32 + k] = v.x;
            tile[(4 * h4 + 1) * 32 + k] = v.y;
            tile[(4 * h4 + 2) * 32 + k] = v.z;
            tile[(4 * h4 + 3) * 32 + k] = v.w;
        }
        __syncthreads();

        float a0 = 0.f;
        const float* kcol = tile + lane;
        #pragma unroll 16
        for (int h = 0; h < H; h++) {
            float2 qv = myqva[h];              // broadcast LDS.64 {q[h], va[h]}
            float  kk = kcol[h * 32];          // conflict-free LDS.32
            a0 = fmaf(qv.y, tanha(qv.x + kk), a0);
        }
        sc[wid * TK + kt + lane] = a0;
    }

    // ---- Phase B: softmax over k (per warp, own row only) ----
    __syncwarp();
    float* myrow = sc + wid * TK;

    float m = -1e30f;
    #pragma unroll
    for (int j = 0; j < 16; j++) m = fmaxf(m, myrow[j * 32 + lane]);
    #pragma unroll
    for (int o = 16; o > 0; o >>= 1)
        m = fmaxf(m, __shfl_xor_sync(0xffffffffu, m, o));

    float ev[16];
    float sum = 0.f;
    #pragma unroll
    for (int j = 0; j < 16; j++) {
        ev[j] = __expf(myrow[j * 32 + lane] - m);
        sum += ev[j];
    }
    #pragma unroll
    for (int o = 16; o > 0; o >>= 1)
        sum += __shfl_xor_sync(0xffffffffu, sum, o);

    const float inv = __fdividef(1.f, sum);
    float* wrow = w_out + (size_t)(b * TQ + q) * TK;
    #pragma unroll
    for (int j = 0; j < 16; j++) {
        float w = ev[j] * inv;
        myrow[j * 32 + lane] = w;
        wrow[j * 32 + lane]  = w;
    }

    // ---- Phase C: context[q][h] = sum_k w[k] * keys[k][h] ----
    float4 acc = make_float4(0.f, 0.f, 0.f, 0.f);
    for (int kt = 0; kt < TK; kt += 32) {
        __syncthreads();   // all warps done with previous tile contents
        const float4* src = (const float4*)(keys + (size_t)(b * TK + kt) * H);
        #pragma unroll
        for (int r = 0; r < 4; r++)
            ((float4*)tile)[threadIdx.x + 256 * r] = src[threadIdx.x + 256 * r];
        __syncthreads();

        #pragma unroll 8
        for (int kk = 0; kk < 32; kk++) {
            float  w  = myrow[kt + kk];
            float4 kv = ((const float4*)(tile + kk * H))[lane];
            acc.x = fmaf(w, kv.x, acc.x);
            acc.y = fmaf(w, kv.y, acc.y);
            acc.z = fmaf(w, kv.z, acc.z);
            acc.w = fmaf(w, kv.w, acc.w);
        }
    }
    ((float4*)(ctx_out + (size_t)(b * TQ + q) * H))[lane] = acc;
}

// ---------------------------------------------------------------------------
extern "C" void kernel_launch(void* const* d_in, const int* in_sizes, int n_in,
                              void* d_out, int out_size)
{
    const float* queries = (const float*)d_in[0];
    const float* keys    = (const float*)d_in[1];
    const float* Wa_w    = (const float*)d_in[2];
    const float* Wa_b    = (const float*)d_in[3];
    const float* Ua_w    = (const float*)d_in[4];
    const float* Ua_b    = (const float*)d_in[5];
    const float* Va_w    = (const float*)d_in[6];
    // Va bias (d_in[7]) cancels in softmax -> unused.

    float* ctx_out = (float*)d_out;                     // (B, TQ, H)
    float* w_out   = ctx_out + BATCH * TQ * H;          // (B, TQ, TK)

    dim3 g1(512 / 16, BATCH, 2);
    proj_kernel<<<g1, 128>>>(queries, keys, Wa_w, Wa_b, Ua_w, Ua_b);

    dim3 g2(TQ / 8, BATCH);
    size_t smem = (32 * H + 8 * TK + 8 * H * 2) * sizeof(float);  // 40960 B
    attn_kernel<<<g2, 256, smem>>>(keys, Va_w, ctx_out, w_out);
}

// round 4
// speedup vs baseline: 1.4408x; 1.4408x over previous
#include <cuda_runtime.h>
#include <cuda_bf16.h>

#define H     128
#define BATCH 8
#define TQ    512
#define TK    512

// Device scratch (allocation-free rule: __device__ globals)
__device__ __align__(16) float g_qp [BATCH * TQ * H];   // [b][q][h]
__device__ __align__(16) float g_kpT[BATCH * H * TK];   // [b][h][k]  (pre-transposed)

__device__ __forceinline__ float tanha(float x) {
    float y;
    asm("tanh.approx.f32 %0, %1;" : "=f"(y) : "f"(x));
    return y;
}

// ---------------------------------------------------------------------------
// Kernel 1: projections.
//   proj==0:  g_qp[b][t][h]  = queries @ Wa_w^T + Wa_b   (normal layout)
//   proj==1:  g_kpT[b][h][t] = keys    @ Ua_w^T + Ua_b   (TRANSPOSED layout)
// grid = (T/16, B, 2), block = 128 (one thread per output column h)
// ---------------------------------------------------------------------------
__global__ void __launch_bounds__(128) proj_kernel(
    const float* __restrict__ queries, const float* __restrict__ keys,
    const float* __restrict__ Wa_w, const float* __restrict__ Wa_b,
    const float* __restrict__ Ua_w, const float* __restrict__ Ua_b)
{
    const int tile = blockIdx.x;   // 32 tiles of 16 rows
    const int b    = blockIdx.y;
    const int proj = blockIdx.z;

    const float* x    = proj == 0 ? queries : keys;
    const float* W    = proj == 0 ? Wa_w    : Ua_w;
    const float* bias = proj == 0 ? Wa_b    : Ua_b;

    const int t0 = tile * 16;
    __shared__ __align__(16) float xs[16][H];

    const float4* xsrc = (const float4*)(x + (size_t)(b * 512 + t0) * H);
    #pragma unroll
    for (int i = threadIdx.x; i < 16 * H / 4; i += 128)
        ((float4*)xs)[i] = xsrc[i];
    __syncthreads();

    const int h = threadIdx.x;
    float acc[16];
    const float bv = bias[h];
    #pragma unroll
    for (int t = 0; t < 16; t++) acc[t] = bv;

    const float4* Wrow = (const float4*)(W + h * H);
    #pragma unroll 4
    for (int i = 0; i < H / 4; i++) {
        float4 w4 = Wrow[i];
        #pragma unroll
        for (int t = 0; t < 16; t++) {
            float4 xv = ((const float4*)xs[t])[i];
            acc[t] = fmaf(xv.x, w4.x, fmaf(xv.y, w4.y, fmaf(xv.z, w4.z, fmaf(xv.w, w4.w, acc[t]))));
        }
    }

    if (proj == 0) {
        #pragma unroll
        for (int t = 0; t < 16; t++)
            g_qp[(size_t)(b * TQ + t0 + t) * H + h] = acc[t];
    } else {
        // transposed: row h, 16 consecutive k -> 4x STG.128 (fire-and-forget)
        float4* dst = (float4*)(g_kpT + ((size_t)b * H + h) * TK + t0);
        #pragma unroll
        for (int i = 0; i < 4; i++)
            dst[i] = make_float4(acc[4*i], acc[4*i+1], acc[4*i+2], acc[4*i+3]);
    }
}

// ---------------------------------------------------------------------------
// Kernel 2: scores + softmax + context. grid (TQ/8, B), block 128 (4 warps).
// Each warp owns 2 queries. Lane owns keys {64t + 2*lane + e}, t=0..7, e=0..1
// -> 16 register score slots per query, 32 total. No __syncthreads.
// ---------------------------------------------------------------------------
__global__ void __launch_bounds__(128) attn_kernel(
    const float* __restrict__ keys,
    const float* __restrict__ Va_w,
    float* __restrict__ ctx_out,   // (B, TQ, H)
    float* __restrict__ w_out)     // (B, TQ, TK)
{
    __shared__ __align__(16) float4 qva[4][H];   // per warp: {q0[h], q1[h], va[h], -}
    __shared__ float wsm[8][TK];                 // softmax weights, per query-in-block

    const int b    = blockIdx.y;
    const int wid  = threadIdx.x >> 5;
    const int lane = threadIdx.x & 31;
    const int q0   = blockIdx.x * 8 + 2 * wid;   // this warp's two queries

    // Stage {q0,q1,va} interleaved (own warp only; syncwarp suffices)
    {
        const float* qp0 = g_qp + (size_t)(b * TQ + q0) * H;
        #pragma unroll
        for (int r = 0; r < 4; r++) {
            int h = lane + 32 * r;
            qva[wid][h] = make_float4(qp0[h], qp0[H + h], Va_w[h], 0.f);
        }
    }
    __syncwarp();

    // ---- Phase A: 32 register accumulators, direct LDG.64 from g_kpT ----
    float a[16], c[16];
    #pragma unroll
    for (int j = 0; j < 16; j++) { a[j] = 0.f; c[j] = 0.f; }

    const float2* kp = (const float2*)(g_kpT + (size_t)b * H * TK + 2 * lane);
    #pragma unroll 2
    for (int h = 0; h < H; h++) {
        float4 qv = qva[wid][h];                 // broadcast LDS.128
        const float2* kr = kp + h * (TK / 2);
        float2 kk[8];
        #pragma unroll
        for (int t = 0; t < 8; t++) kk[t] = kr[t * 32];   // 8 coalesced LDG.64, MLP=8
        #pragma unroll
        for (int t = 0; t < 8; t++) {
            a[2*t]   = fmaf(qv.z, tanha(qv.x + kk[t].x), a[2*t]);
            a[2*t+1] = fmaf(qv.z, tanha(qv.x + kk[t].y), a[2*t+1]);
            c[2*t]   = fmaf(qv.z, tanha(qv.y + kk[t].x), c[2*t]);
            c[2*t+1] = fmaf(qv.z, tanha(qv.y + kk[t].y), c[2*t+1]);
        }
    }

    // ---- Phase B: register softmax (both queries) ----
    float ma = a[0], mc = c[0];
    #pragma unroll
    for (int j = 1; j < 16; j++) { ma = fmaxf(ma, a[j]); mc = fmaxf(mc, c[j]); }
    #pragma unroll
    for (int o = 16; o > 0; o >>= 1) {
        ma = fmaxf(ma, __shfl_xor_sync(0xffffffffu, ma, o));
        mc = fmaxf(mc, __shfl_xor_sync(0xffffffffu, mc, o));
    }
    float sa = 0.f, sc2 = 0.f;
    #pragma unroll
    for (int j = 0; j < 16; j++) {
        a[j] = __expf(a[j] - ma); sa  += a[j];
        c[j] = __expf(c[j] - mc); sc2 += c[j];
    }
    #pragma unroll
    for (int o = 16; o > 0; o >>= 1) {
        sa  += __shfl_xor_sync(0xffffffffu, sa,  o);
        sc2 += __shfl_xor_sync(0xffffffffu, sc2, o);
    }
    const float ia = __fdividef(1.f, sa);
    const float ic = __fdividef(1.f, sc2);

    float* wrow0 = w_out + (size_t)(b * TQ + q0) * TK;
    float* wrow1 = wrow0 + TK;
    #pragma unroll
    for (int t = 0; t < 8; t++) {
        float2 wa = make_float2(a[2*t] * ia, a[2*t+1] * ia);
        float2 wc = make_float2(c[2*t] * ic, c[2*t+1] * ic);
        int off = 64 * t + 2 * lane;
        *(float2*)(wrow0 + off) = wa;            // coalesced STG.64
        *(float2*)(wrow1 + off) = wc;
        *(float2*)(&wsm[2*wid][off])     = wa;   // for phase C broadcast reads
        *(float2*)(&wsm[2*wid + 1][off]) = wc;
    }
    __syncwarp();

    // ---- Phase C: context = w @ keys, direct coalesced LDG.128 of keys ----
    float4 acc0 = make_float4(0.f, 0.f, 0.f, 0.f);
    float4 acc1 = make_float4(0.f, 0.f, 0.f, 0.f);
    const float4* kb = (const float4*)(keys + (size_t)b * TK * H) + lane;
    const float* w0 = wsm[2 * wid];
    const float* w1 = wsm[2 * wid + 1];
    #pragma unroll 8
    for (int key = 0; key < TK; key++) {
        float4 kv = kb[key * (H / 4)];           // coalesced, L1-hot
        float wa = w0[key];                      // broadcast LDS
        float wb = w1[key];
        acc0.x = fmaf(wa, kv.x, acc0.x); acc0.y = fmaf(wa, kv.y, acc0.y);
        acc0.z = fmaf(wa, kv.z, acc0.z); acc0.w = fmaf(wa, kv.w, acc0.w);
        acc1.x = fmaf(wb, kv.x, acc1.x); acc1.y = fmaf(wb, kv.y, acc1.y);
        acc1.z = fmaf(wb, kv.z, acc1.z); acc1.w = fmaf(wb, kv.w, acc1.w);
    }
    float4* crow = (float4*)(ctx_out + (size_t)(b * TQ + q0) * H);
    crow[lane]            = acc0;
    crow[lane + (H / 4)]  = acc1;
}

// ---------------------------------------------------------------------------
extern "C" void kernel_launch(void* const* d_in, const int* in_sizes, int n_in,
                              void* d_out, int out_size)
{
    const float* queries = (const float*)d_in[0];
    const float* keys    = (const float*)d_in[1];
    const float* Wa_w    = (const float*)d_in[2];
    const float* Wa_b    = (const float*)d_in[3];
    const float* Ua_w    = (const float*)d_in[4];
    const float* Ua_b    = (const float*)d_in[5];
    const float* Va_w    = (const float*)d_in[6];
    // Va bias (d_in[7]) cancels in softmax -> unused.

    float* ctx_out = (float*)d_out;                     // (B, TQ, H)
    float* w_out   = ctx_out + BATCH * TQ * H;          // (B, TQ, TK)

    dim3 g1(512 / 16, BATCH, 2);
    proj_kernel<<<g1, 128>>>(queries, keys, Wa_w, Wa_b, Ua_w, Ua_b);

    dim3 g2(TQ / 8, BATCH);
    attn_kernel<<<g2, 128>>>(keys, Va_w, ctx_out, w_out);
}

// round 5
// speedup vs baseline: 1.4566x; 1.0109x over previous
#include <cuda_runtime.h>
#include <cuda_bf16.h>

#define H     128
#define BATCH 8
#define TQ    512
#define TK    512

// Device scratch (allocation-free rule: __device__ globals)
__device__ __align__(16) float g_qp [BATCH * TQ * H];   // [b][q][h]
__device__ __align__(16) float g_kpT[BATCH * H * TK];   // [b][h][k]  (pre-transposed)

__device__ __forceinline__ float tanha(float x) {
    float y;
    asm("tanh.approx.f32 %0, %1;" : "=f"(y) : "f"(x));
    return y;
}

// ---------------------------------------------------------------------------
// Kernel 1: projections.
//   proj==0:  g_qp[b][t][h]  = queries @ Wa_w^T + Wa_b   (normal layout)
//   proj==1:  g_kpT[b][h][t] = keys    @ Ua_w^T + Ua_b   (TRANSPOSED layout)
// grid = (T/16, B, 2), block = 128 (one thread per output column h)
// ---------------------------------------------------------------------------
__global__ void __launch_bounds__(128) proj_kernel(
    const float* __restrict__ queries, const float* __restrict__ keys,
    const float* __restrict__ Wa_w, const float* __restrict__ Wa_b,
    const float* __restrict__ Ua_w, const float* __restrict__ Ua_b)
{
    const int tile = blockIdx.x;   // 32 tiles of 16 rows
    const int b    = blockIdx.y;
    const int proj = blockIdx.z;

    const float* x    = proj == 0 ? queries : keys;
    const float* W    = proj == 0 ? Wa_w    : Ua_w;
    const float* bias = proj == 0 ? Wa_b    : Ua_b;

    const int t0 = tile * 16;
    __shared__ __align__(16) float xs[16][H];

    const float4* xsrc = (const float4*)(x + (size_t)(b * 512 + t0) * H);
    #pragma unroll
    for (int i = threadIdx.x; i < 16 * H / 4; i += 128)
        ((float4*)xs)[i] = xsrc[i];
    __syncthreads();

    const int h = threadIdx.x;
    float acc[16];
    const float bv = bias[h];
    #pragma unroll
    for (int t = 0; t < 16; t++) acc[t] = bv;

    const float4* Wrow = (const float4*)(W + h * H);
    #pragma unroll 4
    for (int i = 0; i < H / 4; i++) {
        float4 w4 = Wrow[i];
        #pragma unroll
        for (int t = 0; t < 16; t++) {
            float4 xv = ((const float4*)xs[t])[i];
            acc[t] = fmaf(xv.x, w4.x, fmaf(xv.y, w4.y, fmaf(xv.z, w4.z, fmaf(xv.w, w4.w, acc[t]))));
        }
    }

    if (proj == 0) {
        #pragma unroll
        for (int t = 0; t < 16; t++)
            g_qp[(size_t)(b * TQ + t0 + t) * H + h] = acc[t];
    } else {
        float4* dst = (float4*)(g_kpT + ((size_t)b * H + h) * TK + t0);
        #pragma unroll
        for (int i = 0; i < 4; i++)
            dst[i] = make_float4(acc[4*i], acc[4*i+1], acc[4*i+2], acc[4*i+3]);
    }
}

// ---------------------------------------------------------------------------
// Kernel 2: scores + softmax. grid (TQ/4, B), block 128 (4 warps).
// ONE query per warp -> 4096 warps chip-wide (~7/SMSP) for latency hiding.
// Lane owns keys {64t + 2*lane + e}, t=0..7, e=0..1 -> 16 register slots.
// ---------------------------------------------------------------------------
__global__ void __launch_bounds__(128) score_kernel(
    const float* __restrict__ Va_w,
    float* __restrict__ w_out)     // (B, TQ, TK)
{
    __shared__ __align__(8) float2 qva[4][H];    // per warp: {q[h], va[h]}

    const int b    = blockIdx.y;
    const int wid  = threadIdx.x >> 5;
    const int lane = threadIdx.x & 31;
    const int q    = blockIdx.x * 4 + wid;

    {
        const float* qp = g_qp + (size_t)(b * TQ + q) * H;
        #pragma unroll
        for (int r = 0; r < 4; r++) {
            int h = lane + 32 * r;
            qva[wid][h] = make_float2(qp[h], Va_w[h]);
        }
    }
    __syncwarp();

    // ---- Phase A: 16 independent accumulators, coalesced LDG.64 of kpT ----
    float a[16];
    #pragma unroll
    for (int j = 0; j < 16; j++) a[j] = 0.f;

    const float2* kp = (const float2*)(g_kpT + (size_t)b * H * TK) + lane;
    #pragma unroll 2
    for (int h = 0; h < H; h++) {
        float2 qv = qva[wid][h];                 // broadcast LDS.64 {q[h], va[h]}
        const float2* kr = kp + h * (TK / 2);
        float2 kk[8];
        #pragma unroll
        for (int t = 0; t < 8; t++) kk[t] = kr[t * 32];   // MLP=8 coalesced LDG.64
        #pragma unroll
        for (int t = 0; t < 8; t++) {
            a[2*t]   = fmaf(qv.y, tanha(qv.x + kk[t].x), a[2*t]);
            a[2*t+1] = fmaf(qv.y, tanha(qv.x + kk[t].y), a[2*t+1]);
        }
    }

    // ---- Phase B: register softmax ----
    float m = a[0];
    #pragma unroll
    for (int j = 1; j < 16; j++) m = fmaxf(m, a[j]);
    #pragma unroll
    for (int o = 16; o > 0; o >>= 1)
        m = fmaxf(m, __shfl_xor_sync(0xffffffffu, m, o));

    float s = 0.f;
    #pragma unroll
    for (int j = 0; j < 16; j++) { a[j] = __expf(a[j] - m); s += a[j]; }
    #pragma unroll
    for (int o = 16; o > 0; o >>= 1)
        s += __shfl_xor_sync(0xffffffffu, s, o);

    const float inv = __fdividef(1.f, s);
    float* wrow = w_out + (size_t)(b * TQ + q) * TK;
    #pragma unroll
    for (int t = 0; t < 8; t++)
        *(float2*)(wrow + 64 * t + 2 * lane) =
            make_float2(a[2*t] * inv, a[2*t+1] * inv);
}

// ---------------------------------------------------------------------------
// Kernel 3: context = w @ keys. grid (TQ/8, B), block 128 (4 warps).
// Two queries per warp so each key float4 is amortized over 2 queries.
// ---------------------------------------------------------------------------
__global__ void __launch_bounds__(128) ctx_kernel(
    const float* __restrict__ keys,
    const float* __restrict__ w_in,    // (B, TQ, TK)
    float* __restrict__ ctx_out)       // (B, TQ, H)
{
    __shared__ float wsm[8][TK];

    const int b    = blockIdx.y;
    const int wid  = threadIdx.x >> 5;
    const int lane = threadIdx.x & 31;
    const int q0   = blockIdx.x * 8 + 2 * wid;

    // Stage this warp's 2 weight rows (contiguous 1024 floats) into smem
    {
        const float4* src = (const float4*)(w_in + (size_t)(b * TQ + q0) * TK);
        float4* dst = (float4*)&wsm[2 * wid][0];
        #pragma unroll
        for (int i = 0; i < 8; i++)
            dst[lane + 32 * i] = src[lane + 32 * i];
    }
    __syncwarp();

    float4 acc0 = make_float4(0.f, 0.f, 0.f, 0.f);
    float4 acc1 = make_float4(0.f, 0.f, 0.f, 0.f);
    const float4* kb = (const float4*)(keys + (size_t)b * TK * H) + lane;
    const float* w0 = wsm[2 * wid];
    const float* w1 = wsm[2 * wid + 1];
    #pragma unroll 8
    for (int key = 0; key < TK; key++) {
        float4 kv = kb[key * (H / 4)];           // coalesced LDG.128, L1/L2-hot
        float wa = w0[key];                      // broadcast LDS
        float wb = w1[key];
        acc0.x = fmaf(wa, kv.x, acc0.x); acc0.y = fmaf(wa, kv.y, acc0.y);
        acc0.z = fmaf(wa, kv.z, acc0.z); acc0.w = fmaf(wa, kv.w, acc0.w);
        acc1.x = fmaf(wb, kv.x, acc1.x); acc1.y = fmaf(wb, kv.y, acc1.y);
        acc1.z = fmaf(wb, kv.z, acc1.z); acc1.w = fmaf(wb, kv.w, acc1.w);
    }
    float4* crow = (float4*)(ctx_out + (size_t)(b * TQ + q0) * H);
    crow[lane]           = acc0;
    crow[lane + (H / 4)] = acc1;
}

// ---------------------------------------------------------------------------
extern "C" void kernel_launch(void* const* d_in, const int* in_sizes, int n_in,
                              void* d_out, int out_size)
{
    const float* queries = (const float*)d_in[0];
    const float* keys    = (const float*)d_in[1];
    const float* Wa_w    = (const float*)d_in[2];
    const float* Wa_b    = (const float*)d_in[3];
    const float* Ua_w    = (const float*)d_in[4];
    const float* Ua_b    = (const float*)d_in[5];
    const float* Va_w    = (const float*)d_in[6];
    // Va bias (d_in[7]) cancels in softmax -> unused.

    float* ctx_out = (float*)d_out;                     // (B, TQ, H)
    float* w_out   = ctx_out + BATCH * TQ * H;          // (B, TQ, TK)

    dim3 g1(512 / 16, BATCH, 2);
    proj_kernel<<<g1, 128>>>(queries, keys, Wa_w, Wa_b, Ua_w, Ua_b);

    dim3 g2(TQ / 4, BATCH);
    score_kernel<<<g2, 128>>>(Va_w, w_out);

    dim3 g3(TQ / 8, BATCH);
    ctx_kernel<<<g3, 128>>>(keys, w_out, ctx_out);
}